// round 8
// baseline (speedup 1.0000x reference)
#include <cuda_runtime.h>
#include <math_constants.h>

// Problem constants (fixed by the reference)
#define BB 2
#define TT 512
#define EE 1024
#define SS 2048
#define AA 30

#define GSZ 4                    // spans per group (same t0)
#define NBINS (TT * AA)          // counting-sort key = t0*30 + (w-1)
#define NGROUPS_MAX 2048

#define BUCKET 16                // t0 values per bucket
#define NBUCK  (TT / BUCKET)     // 32
#define ROWS_MAX (BUCKET + AA - 1)   // 45 rows per tile
#define EQ   128                 // floats per E-slice
#define NH   (EE / EQ)           // 8 slices
#define C4Q  (EQ / 4)            // 32 float4 per tile row
#define TILE_BYTES (ROWS_MAX * C4Q * 16)   // 23040 B

__device__ float g_scores[BB * TT];
__device__ float g_probs[BB * SS * 32];
__device__ int   g_sorted[SS];
__device__ int4  g_groups[NGROUPS_MAX];
__device__ int   g_t0_goff[TT + 1];      // exclusive group offsets per t0

// ---------------------------------------------------------------------------
// Kernel 1: scores[b,t] = relu(dot(x[b,t,:], W) + bias). Block per row.
// ---------------------------------------------------------------------------
__global__ __launch_bounds__(256)
void score_kernel(const float* __restrict__ x,
                  const float* __restrict__ W,
                  const float* __restrict__ bias) {
    __shared__ float red[8];
    const int row  = blockIdx.x;
    const int tid  = threadIdx.x;
    const int lane = tid & 31;
    const int wrp  = tid >> 5;

    const float4 xv = reinterpret_cast<const float4*>(x)[(size_t)row * 256 + tid];
    const float4 wv = reinterpret_cast<const float4*>(W)[tid];
    float acc = xv.x * wv.x + xv.y * wv.y + xv.z * wv.z + xv.w * wv.w;

#pragma unroll
    for (int off = 16; off; off >>= 1)
        acc += __shfl_xor_sync(0xffffffffu, acc, off);
    if (lane == 0) red[wrp] = acc;
    __syncthreads();

    if (wrp == 0) {
        float v = (lane < 8) ? red[lane] : 0.0f;
#pragma unroll
        for (int off = 4; off; off >>= 1)
            v += __shfl_xor_sync(0xffffffffu, v, off);
        if (lane == 0)
            g_scores[row] = fmaxf(v + bias[0], 0.0f);
    }
}

// ---------------------------------------------------------------------------
// Kernel 2: softmax probs per (b,s) -> g_probs[b][s][lane] (0 for lane >= w).
// ---------------------------------------------------------------------------
__global__ __launch_bounds__(256)
void prob_kernel(const int* __restrict__ start,
                 const int* __restrict__ end) {
    const int wid  = blockIdx.x * 8 + (threadIdx.x >> 5);   // 0 .. B*S-1
    const int lane = threadIdx.x & 31;
    const int s = wid & (SS - 1);
    const int b = wid >> 11;

    const int t0 = start[s];
    const int w  = end[s] - t0 + 1;                          // 1..30

    float sc = (lane < w) ? g_scores[b * TT + t0 + lane] : -CUDART_INF_F;
    float m = sc;
#pragma unroll
    for (int off = 16; off; off >>= 1)
        m = fmaxf(m, __shfl_xor_sync(0xffffffffu, m, off));
    float e = (lane < w) ? __expf(sc - m) : 0.0f;
    float sum = e;
#pragma unroll
    for (int off = 16; off; off >>= 1)
        sum += __shfl_xor_sync(0xffffffffu, sum, off);

    g_probs[((size_t)b * SS + s) * 32 + lane] = e / sum;
}

// ---------------------------------------------------------------------------
// Kernel 3: counting sort of spans by (t0, w) + DETERMINISTIC group layout.
// Single block, 1024 threads, 60 KB dynamic smem for bins.
// Groups of <=4 spans per t0, widths ascending; group offsets per t0 from an
// exclusive scan so group order is deterministic and sorted by t0.
// ---------------------------------------------------------------------------
extern __shared__ int sm_bins[];

__global__ __launch_bounds__(1024)
void sort_kernel(const int* __restrict__ start,
                 const int* __restrict__ end) {
    int* bins = sm_bins;                 // [NBINS]
    __shared__ int t0_off[TT + 1];
    __shared__ int gof[TT + 1];
    __shared__ int aux[32];
    __shared__ int aux2[16];

    const int tid  = threadIdx.x;
    const int lane = tid & 31;
    const int wrp  = tid >> 5;

    for (int i = tid; i < NBINS; i += 1024) bins[i] = 0;
    __syncthreads();

    // histogram over (t0, w)
    for (int s = tid; s < SS; s += 1024) {
        const int t0 = start[s];
        const int w  = end[s] - t0 + 1;
        atomicAdd(&bins[t0 * AA + (w - 1)], 1);
    }
    __syncthreads();

    // exclusive scan over NBINS (15 per thread + 2-level block scan)
    const int base = tid * (NBINS / 1024);
    int v[NBINS / 1024];
    int run = 0;
#pragma unroll
    for (int c = 0; c < NBINS / 1024; ++c) { v[c] = bins[base + c]; run += v[c]; }

    int inc = run;
#pragma unroll
    for (int off = 1; off < 32; off <<= 1) {
        const int t = __shfl_up_sync(0xffffffffu, inc, off);
        if (lane >= off) inc += t;
    }
    if (lane == 31) aux[wrp] = inc;
    __syncthreads();
    if (wrp == 0) {
        int a = aux[lane];
#pragma unroll
        for (int off = 1; off < 32; off <<= 1) {
            const int t = __shfl_up_sync(0xffffffffu, a, off);
            if (lane >= off) a += t;
        }
        aux[lane] = a;
    }
    __syncthreads();
    int ex = inc - run + (wrp ? aux[wrp - 1] : 0);
#pragma unroll
    for (int c = 0; c < NBINS / 1024; ++c) { const int t = v[c]; bins[base + c] = ex; ex += t; }
    __syncthreads();

    // snapshot per-t0 span offsets before scatter mutates bins
    if (tid < TT) t0_off[tid] = bins[tid * AA];
    if (tid == 0) t0_off[TT] = SS;
    __syncthreads();

    // scatter -> g_sorted (sorted by t0, then w ascending)
    for (int s = tid; s < SS; s += 1024) {
        const int t0 = start[s];
        const int w  = end[s] - t0 + 1;
        const int pos = atomicAdd(&bins[t0 * AA + (w - 1)], 1);
        g_sorted[pos] = s;
    }
    __syncthreads();

    // scan of per-t0 group counts (512 values; warps 0..15 fully active)
    int gc = 0;
    if (tid < TT) {
        const int n = t0_off[tid + 1] - t0_off[tid];
        gc = (n + GSZ - 1) / GSZ;
    }
    if (tid < TT) {
        int gi = gc;
#pragma unroll
        for (int off = 1; off < 32; off <<= 1) {
            const int t = __shfl_up_sync(0xffffffffu, gi, off);
            if (lane >= off) gi += t;
        }
        if (lane == 31) aux2[wrp] = gi;
        __syncthreads();
        if (wrp == 0 && lane < 16) {
            int a = aux2[lane];
#pragma unroll
            for (int off = 1; off < 16; off <<= 1) {
                const int t = __shfl_up_sync(0x0000ffffu, a, off);
                if (lane >= off) a += t;
            }
            aux2[lane] = a;
        }
        __syncthreads();
        const int incl = gi + (wrp ? aux2[wrp - 1] : 0);
        gof[tid + 1] = incl;
        if (tid == 0) gof[0] = 0;
    } else {
        __syncthreads();
        __syncthreads();
    }
    __syncthreads();

    // emit groups deterministically + publish per-t0 group offsets
    if (tid <= TT) g_t0_goff[tid] = gof[tid];
    if (tid < TT) {
        const int b0 = t0_off[tid];
        const int n  = t0_off[tid + 1] - b0;
        const int g0 = gof[tid];
        for (int k = 0, gi = 0; k < n; k += GSZ, ++gi)
            g_groups[g0 + gi] = make_int4(b0 + k, min(GSZ, n - k), tid, 0);
    }
}

// ---------------------------------------------------------------------------
// Kernel 4: tiled + grouped + tiered span pooling.
// Block = (bucket kb, E-slice h, batch b x group-half). 1024 blocks, 23 KB.
//  - tile: x rows [16kb, 16kb+45) x EQ floats in smem (loaded once)
//  - each warp takes groups (stride 16 with the half split) from the bucket
//  - per group: 4 spans, widths ascending; 4 cascaded loops drop finished
//    spans, so no zero-prob FMA. Row data from smem, probs via scalar LDG
//    (uniform -> broadcast, L1-resident).
// ---------------------------------------------------------------------------
extern __shared__ char smem_raw[];

__global__ __launch_bounds__(256)
void main_kernel(const float* __restrict__ x,
                 const int* __restrict__ end,
                 float* __restrict__ out) {
    float4* tile = reinterpret_cast<float4*>(smem_raw);    // [ROWS_MAX][C4Q]

    const int tid  = threadIdx.x;
    const int lane = tid & 31;
    const int wrp  = tid >> 5;
    const int kb   = blockIdx.x;
    const int h    = blockIdx.y;
    const int bz   = blockIdx.z;
    const int b    = bz >> 1;
    const int half = bz & 1;
    const int base = kb * BUCKET;

    // ---- load tile ----
    const int nr = min(ROWS_MAX, TT - base);
    const float4* __restrict__ x4 =
        reinterpret_cast<const float4*>(x) + ((size_t)b * TT + base) * 256 + h * C4Q;
    for (int i = tid; i < nr * C4Q; i += 256) {
        const int r = i >> 5;
        const int c = i & (C4Q - 1);
        tile[i] = x4[(size_t)r * 256 + c];
    }
    __syncthreads();

    const int g0 = g_t0_goff[base];
    const int g1 = g_t0_goff[base + BUCKET];
    const float* __restrict__ pbase = g_probs + (size_t)b * SS * 32;

    for (int idx = g0 + half * 8 + wrp; idx < g1; idx += 16) {
        const int4 gd = g_groups[idx];            // span base, cnt, t0
        const int sb = gd.x, cnt = gd.y, t0 = gd.z;

        int s[GSZ], w[GSZ];
        const float* pp[GSZ];
#pragma unroll
        for (int g = 0; g < GSZ; ++g) {
            s[g]  = g_sorted[sb + min(g, cnt - 1)];
            w[g]  = end[s[g]] - t0 + 1;           // ascending in g
            pp[g] = pbase + (size_t)s[g] * 32;
        }

        const float4* __restrict__ trow = tile + (t0 - base) * C4Q + lane;

        float4 A0 = make_float4(0.f,0.f,0.f,0.f);
        float4 A1 = make_float4(0.f,0.f,0.f,0.f);
        float4 A2 = make_float4(0.f,0.f,0.f,0.f);
        float4 A3 = make_float4(0.f,0.f,0.f,0.f);

        int j = 0;
#pragma unroll 2
        for (; j < w[0]; ++j) {                    // all 4 spans active
            const float4 v = trow[j * C4Q];
            const float p0 = __ldg(pp[0] + j);
            const float p1 = __ldg(pp[1] + j);
            const float p2 = __ldg(pp[2] + j);
            const float p3 = __ldg(pp[3] + j);
            A0.x += p0*v.x; A0.y += p0*v.y; A0.z += p0*v.z; A0.w += p0*v.w;
            A1.x += p1*v.x; A1.y += p1*v.y; A1.z += p1*v.z; A1.w += p1*v.w;
            A2.x += p2*v.x; A2.y += p2*v.y; A2.z += p2*v.z; A2.w += p2*v.w;
            A3.x += p3*v.x; A3.y += p3*v.y; A3.z += p3*v.z; A3.w += p3*v.w;
        }
#pragma unroll 2
        for (; j < w[1]; ++j) {                    // spans 1..3
            const float4 v = trow[j * C4Q];
            const float p1 = __ldg(pp[1] + j);
            const float p2 = __ldg(pp[2] + j);
            const float p3 = __ldg(pp[3] + j);
            A1.x += p1*v.x; A1.y += p1*v.y; A1.z += p1*v.z; A1.w += p1*v.w;
            A2.x += p2*v.x; A2.y += p2*v.y; A2.z += p2*v.z; A2.w += p2*v.w;
            A3.x += p3*v.x; A3.y += p3*v.y; A3.z += p3*v.z; A3.w += p3*v.w;
        }
#pragma unroll 2
        for (; j < w[2]; ++j) {                    // spans 2..3
            const float4 v = trow[j * C4Q];
            const float p2 = __ldg(pp[2] + j);
            const float p3 = __ldg(pp[3] + j);
            A2.x += p2*v.x; A2.y += p2*v.y; A2.z += p2*v.z; A2.w += p2*v.w;
            A3.x += p3*v.x; A3.y += p3*v.y; A3.z += p3*v.z; A3.w += p3*v.w;
        }
#pragma unroll 2
        for (; j < w[3]; ++j) {                    // span 3 only
            const float4 v = trow[j * C4Q];
            const float p3 = __ldg(pp[3] + j);
            A3.x += p3*v.x; A3.y += p3*v.y; A3.z += p3*v.z; A3.w += p3*v.w;
        }

        float4* __restrict__ o4 = reinterpret_cast<float4*>(out);
        const size_t obase = (size_t)b * SS * 256 + (size_t)h * C4Q + lane;
        o4[obase + (size_t)s[0] * 256] = A0;
        if (cnt > 1) o4[obase + (size_t)s[1] * 256] = A1;
        if (cnt > 2) o4[obase + (size_t)s[2] * 256] = A2;
        if (cnt > 3) o4[obase + (size_t)s[3] * 256] = A3;
    }
}

// ---------------------------------------------------------------------------
// Launch
// Inputs (metadata order): x (B,T,E) f32, W (E,1) f32, b (1,) f32,
//                          start (S,) i32, end (S,) i32
// Output: (B, S, E) f32
// ---------------------------------------------------------------------------
extern "C" void kernel_launch(void* const* d_in, const int* in_sizes, int n_in,
                              void* d_out, int out_size) {
    const float* x     = (const float*)d_in[0];
    const float* W     = (const float*)d_in[1];
    const float* bias  = (const float*)d_in[2];
    const int*   start = (const int*)d_in[3];
    const int*   end   = (const int*)d_in[4];
    float*       out   = (float*)d_out;

    static bool attr_done = false;
    if (!attr_done) {
        cudaFuncSetAttribute(sort_kernel,
                             cudaFuncAttributeMaxDynamicSharedMemorySize,
                             NBINS * 4);
        attr_done = true;
    }

    score_kernel<<<BB * TT, 256>>>(x, W, bias);
    prob_kernel<<<(BB * SS) / 8, 256>>>(start, end);
    sort_kernel<<<1, 1024, NBINS * 4>>>(start, end);

    dim3 grid(NBUCK, NH, BB * 2);
    main_kernel<<<grid, 256, TILE_BYTES>>>(x, end, out);
}

// round 9
// speedup vs baseline: 1.3801x; 1.3801x over previous
#include <cuda_runtime.h>
#include <math_constants.h>

// Problem constants (fixed by the reference)
#define BB 2
#define TT 512
#define EE 1024
#define SS 2048
#define AA 30

// Scratch for precomputed head scores: relu(x @ W + b), shape (B*T)
__device__ float g_scores[BB * TT];

// ---------------------------------------------------------------------------
// Kernel 1: scores[b,t] = relu(dot(x[b,t,:], W) + bias)
// One warp per row, ILP=8. 1024 rows -> 128 blocks x 8 warps.
// ---------------------------------------------------------------------------
__global__ __launch_bounds__(256)
void score_kernel(const float* __restrict__ x,
                  const float* __restrict__ W,
                  const float* __restrict__ bias) {
    const int row  = blockIdx.x * 8 + (threadIdx.x >> 5);   // B*T = 1024 rows
    const int lane = threadIdx.x & 31;

    const float4* __restrict__ xr = reinterpret_cast<const float4*>(x) + (size_t)row * 256;
    const float4* __restrict__ w4 = reinterpret_cast<const float4*>(W);

    float acc = 0.0f;
#pragma unroll
    for (int i = 0; i < 8; ++i) {
        const float4 xv = xr[lane + i * 32];
        const float4 wv = w4[lane + i * 32];
        acc += xv.x * wv.x + xv.y * wv.y + xv.z * wv.z + xv.w * wv.w;
    }
#pragma unroll
    for (int off = 16; off; off >>= 1)
        acc += __shfl_xor_sync(0xffffffffu, acc, off);

    if (lane == 0)
        g_scores[row] = fmaxf(acc + bias[0], 0.0f);
}

// ---------------------------------------------------------------------------
// Kernel 2: block per (s, b), 256 threads.
//   warp 0: softmax over <=30 valid scores -> smem p[32] (zero-padded)
//   all threads: out[b,s,tid*4..] = sum_j p[j] * x[b, min(t0+j,T-1), ...]
//   j-loop unrolled x4 with clamped row indices -> uniform MLP=4.
// ---------------------------------------------------------------------------
__global__ __launch_bounds__(256)
void span_kernel(const float* __restrict__ x,
                 const int* __restrict__ start,
                 const int* __restrict__ end,
                 float* __restrict__ out) {
    const int s = blockIdx.x;
    const int b = blockIdx.y;

    const int t0 = start[s];
    const int w  = end[s] - t0 + 1;   // 1..30

    __shared__ float p[32];

    const int tid = threadIdx.x;
    if (tid < 32) {
        const float sc = (tid < w) ? g_scores[b * TT + t0 + tid] : -CUDART_INF_F;
        float m = sc;
#pragma unroll
        for (int off = 16; off; off >>= 1)
            m = fmaxf(m, __shfl_xor_sync(0xffffffffu, m, off));
        const float e = (tid < w) ? __expf(sc - m) : 0.0f;
        float sum = e;
#pragma unroll
        for (int off = 16; off; off >>= 1)
            sum += __shfl_xor_sync(0xffffffffu, sum, off);
        p[tid] = e / sum;             // exactly 0 for tid >= w
    }
    __syncthreads();

    // Each thread owns one float4 column of E (256 * 4 = 1024).
    const float4* __restrict__ xb =
        reinterpret_cast<const float4*>(x) + (size_t)b * TT * 256 + tid;

    float4 acc = make_float4(0.0f, 0.0f, 0.0f, 0.0f);

#pragma unroll 1
    for (int j = 0; j < w; j += 4) {
        // clamped row indices (reference clamps span_idx to T-1 the same way;
        // p[j]=0 past w makes the clamped rows contribute nothing)
        const int r0 = min(t0 + j,     TT - 1);
        const int r1 = min(t0 + j + 1, TT - 1);
        const int r2 = min(t0 + j + 2, TT - 1);
        const int r3 = min(t0 + j + 3, TT - 1);

        const float p0 = p[j];
        const float p1 = p[j + 1];
        const float p2 = p[j + 2];
        const float p3 = p[j + 3];

        const float4 v0 = xb[(size_t)r0 * 256];
        const float4 v1 = xb[(size_t)r1 * 256];
        const float4 v2 = xb[(size_t)r2 * 256];
        const float4 v3 = xb[(size_t)r3 * 256];

        acc.x += p0 * v0.x + p1 * v1.x + p2 * v2.x + p3 * v3.x;
        acc.y += p0 * v0.y + p1 * v1.y + p2 * v2.y + p3 * v3.y;
        acc.z += p0 * v0.z + p1 * v1.z + p2 * v2.z + p3 * v3.z;
        acc.w += p0 * v0.w + p1 * v1.w + p2 * v2.w + p3 * v3.w;
    }

    reinterpret_cast<float4*>(out)[((size_t)b * SS + s) * 256 + tid] = acc;
}

// ---------------------------------------------------------------------------
// Launch
// Inputs (metadata order): x (B,T,E) f32, W (E,1) f32, b (1,) f32,
//                          start (S,) i32, end (S,) i32
// Output: (B, S, E) f32
// ---------------------------------------------------------------------------
extern "C" void kernel_launch(void* const* d_in, const int* in_sizes, int n_in,
                              void* d_out, int out_size) {
    const float* x     = (const float*)d_in[0];
    const float* W     = (const float*)d_in[1];
    const float* bias  = (const float*)d_in[2];
    const int*   start = (const int*)d_in[3];
    const int*   end   = (const int*)d_in[4];
    float*       out   = (float*)d_out;

    // Kernel 1: scores, warp per row
    score_kernel<<<(BB * TT) / 8, 256>>>(x, W, bias);

    // Kernel 2: block per (span, batch)
    dim3 grid(SS, BB);
    span_kernel<<<grid, 256>>>(x, start, end, out);
}